// round 12
// baseline (speedup 1.0000x reference)
#include <cuda_runtime.h>

#define IMG_W 512
#define IMG_H 512
#define NBATCH 32
#define RSTRIP 16
#define BLOCK 256
#define RDEPTH 5
// threads: 32 batches * (512/16 y-strips) * (512/4 x-strips) = 131072
#define TOTAL_THREADS (NBATCH * (IMG_H / RSTRIP) * (IMG_W / 4))
#define NBLOCKS (TOTAL_THREADS / BLOCK)   // 512
#define NPIX ((long long)NBATCH * IMG_H * IMG_W)

__device__ float2 g_partials[NBLOCKS];
__device__ unsigned int g_ticket = 0;     // reset by the last block each call

// Load one full 6-wide row (float4 body + 2 halo scalars). All three loads are
// independent of any prior register state -> they can stay outstanding for the
// full prefetch distance.
__device__ __forceinline__ void load_row6(const float* __restrict__ img, int y,
                                          int x0, float v[6]) {
    if ((unsigned)y < IMG_H) {
        const float* row = img + (size_t)y * IMG_W;
        float4 m = __ldg(reinterpret_cast<const float4*>(row + x0));
        v[1] = m.x; v[2] = m.y; v[3] = m.z; v[4] = m.w;
        v[0] = (x0 > 0)         ? __ldg(row + x0 - 1) : 0.f;
        v[5] = (x0 + 4 < IMG_W) ? __ldg(row + x0 + 4) : 0.f;
    } else {
#pragma unroll
        for (int k = 0; k < 6; ++k) v[k] = 0.f;
    }
}

// Sobel magnitude |Gx|+|Gy| for 4 pixels from 3 raw rows (column-sum form;
// same op count as the dh/sh form, no per-row derived state needed).
__device__ __forceinline__ void sobel4(const float r0[6], const float r1[6],
                                       const float r2[6], float s[4]) {
    float c[6], d[6];
#pragma unroll
    for (int j = 0; j < 6; ++j) {
        c[j] = r0[j] + 2.f * r1[j] + r2[j];   // vertical [1,2,1]
        d[j] = r0[j] - r2[j];                 // vertical [1,0,-1]
    }
#pragma unroll
    for (int j = 0; j < 4; ++j) {
        float gx = c[j + 2] - c[j];                       // horiz [-1,0,1]
        float gy = d[j] + 2.f * d[j + 1] + d[j + 2];      // horiz [1,2,1]
        s[j] = fabsf(gx) + fabsf(gy);
    }
}

__global__ __launch_bounds__(BLOCK, 2)   // 2 blocks/SM, regs capped at 128
void fuse_main(const float* __restrict__ A, const float* __restrict__ Bi,
               const float* __restrict__ F, const int* __restrict__ scheme,
               float* __restrict__ out) {
    int t   = blockIdx.x * BLOCK + threadIdx.x;
    int b   = t >> 12;          // / 4096 strips per image
    int rem = t & 4095;
    int ys  = rem >> 7;         // 32 y-strips
    int xs  = rem & 127;        // 128 x-strips
    int x0  = xs << 2;
    int y0  = ys * RSTRIP;

    size_t off = (size_t)b * IMG_H * IMG_W;
    const float* pA = A  + off;
    const float* pB = Bi + off;
    const float* pF = F  + off;
    // JAX default x64-disabled: fuse_scheme materializes as int32
    const bool avg = (scheme[b] == 0);

    // 5-deep raw-row rings; row index ri (0..RSTRIP+1) lives in slot ri%5.
    float rgA[RDEPTH][6], rgB[RDEPTH][6], rgF[RDEPTH][6];
    float sumL = 0.f, sumG = 0.f;

    // Prologue: rows ri=0,1 (y = y0-1, y0). Rows ri>=2 arrive via distance-2
    // prefetch inside the loop.
    load_row6(pA, y0 - 1, x0, rgA[0]);
    load_row6(pB, y0 - 1, x0, rgB[0]);
    load_row6(pF, y0 - 1, x0, rgF[0]);
    load_row6(pA, y0,     x0, rgA[1]);
    load_row6(pB, y0,     x0, rgB[1]);
    load_row6(pF, y0,     x0, rgF[1]);

#pragma unroll
    for (int i = 0; i < RSTRIP + 2; ++i) {
        // 1) Prefetch row i+2 into slot (i+2)%5 (overwrites dead row i-3).
        //    No consumer for two iterations -> 6 float4 + 6 scalars in flight.
        if (i + 2 < RSTRIP + 2) {
            int s = (i + 2) % RDEPTH;
            int y = y0 + 1 + i;
            load_row6(pA, y, x0, rgA[s]);
            load_row6(pB, y, x0, rgB[s]);
            load_row6(pF, y, x0, rgF[s]);
        }

        int cur = i % RDEPTH;

        // l_loss contribution: rows y0 .. y0+R-1  (i in [1, R])
        if (i >= 1 && i <= RSTRIP) {
#pragma unroll
            for (int j = 0; j < 4; ++j) {
                float ab = avg ? 0.5f * (rgA[cur][j + 1] + rgB[cur][j + 1])
                               : fmaxf(rgA[cur][j + 1], rgB[cur][j + 1]);
                sumL += fabsf(ab - rgF[cur][j + 1]);
            }
        }

        // grad_loss for output row y-1 once rows i-2, i-1, i are resident
        if (i >= 2) {
            int r0 = (i - 2) % RDEPTH, r1 = (i - 1) % RDEPTH;
            float sA[4], sB[4], sF[4];
            sobel4(rgA[r0], rgA[r1], rgA[cur], sA);
            sobel4(rgB[r0], rgB[r1], rgB[cur], sB);
            sobel4(rgF[r0], rgF[r1], rgF[cur], sF);
#pragma unroll
            for (int j = 0; j < 4; ++j)
                sumG += fabsf(sF[j] - fmaxf(sA[j], sB[j]));
        }
    }

    // ---- Block reduction (deterministic, no float atomics) ----
#pragma unroll
    for (int o = 16; o > 0; o >>= 1) {
        sumL += __shfl_down_sync(0xffffffffu, sumL, o);
        sumG += __shfl_down_sync(0xffffffffu, sumG, o);
    }
    __shared__ float sL[BLOCK / 32], sG[BLOCK / 32];
    __shared__ bool s_last;
    int lane = threadIdx.x & 31, wid = threadIdx.x >> 5;
    if (lane == 0) { sL[wid] = sumL; sG[wid] = sumG; }
    __syncthreads();
    if (threadIdx.x == 0) {
        float l = 0.f, g = 0.f;
#pragma unroll
        for (int k = 0; k < BLOCK / 32; ++k) { l += sL[k]; g += sG[k]; }
        g_partials[blockIdx.x] = make_float2(l, g);
        __threadfence();
        unsigned int ticket = atomicAdd(&g_ticket, 1u);
        s_last = (ticket == NBLOCKS - 1);
    }
    __syncthreads();

    // ---- Last block finalizes: fixed-order sum over all partials ----
    if (s_last) {
        float l = 0.f, g = 0.f;
#pragma unroll
        for (int k = 0; k < NBLOCKS / BLOCK; ++k) {
            float2 p = g_partials[threadIdx.x + k * BLOCK];
            l += p.x; g += p.y;
        }
#pragma unroll
        for (int o = 16; o > 0; o >>= 1) {
            l += __shfl_down_sync(0xffffffffu, l, o);
            g += __shfl_down_sync(0xffffffffu, g, o);
        }
        if (lane == 0) { sL[wid] = l; sG[wid] = g; }
        __syncthreads();
        if (threadIdx.x == 0) {
            float L = 0.f, G = 0.f;
#pragma unroll
            for (int k = 0; k < BLOCK / 32; ++k) { L += sL[k]; G += sG[k]; }
            out[0] = (L + G) * (1.0f / (float)NPIX);  // l_loss + grad_loss; 0.0*cs_loss dropped
            g_ticket = 0;   // reset for next graph replay
        }
    }
}

extern "C" void kernel_launch(void* const* d_in, const int* in_sizes, int n_in,
                              void* d_out, int out_size) {
    (void)in_sizes; (void)n_in; (void)out_size;
    const float* A      = (const float*)d_in[0];
    const float* B      = (const float*)d_in[1];
    const float* F      = (const float*)d_in[2];
    const int*   scheme = (const int*)d_in[3];
    float* out = (float*)d_out;

    fuse_main<<<NBLOCKS, BLOCK>>>(A, B, F, scheme, out);
}